// round 16
// baseline (speedup 1.0000x reference)
#include <cuda_runtime.h>
#include <cuda_fp16.h>
#include <cstdint>

// Problem constants
#define S_    2048
#define B_    2
#define E_    1024
#define H_    16
#define D_    64
#define HD_   1024
#define Q3_   3072
#define NROWS (S_ * B_)   // 4096 rows, row index = s*B + b
#define BH_   32          // b*16 + h
#define NCTA_FULL 296     // 148 SMs x 2 CTAs/SM (measured GEMM occupancy)

// ---------------------------------------------------------------------------
// Scratch (device globals: cudaMalloc is forbidden by the harness)
// ---------------------------------------------------------------------------
__device__ __align__(16) __half g_a0[(size_t)NROWS * E_];   // LN out (fp16)
__device__ __align__(16) __half g_wq[(size_t)Q3_ * E_];     // w_qkv^T fp16 [3072,1024]
__device__ __align__(16) __half g_wo[(size_t)E_ * HD_];     // w_out^T fp16 [1024,1024]
// Attention operands (single fp16), written by the QKV GEMM epilogue:
__device__ __align__(16) __half g_q0[(size_t)BH_ * S_ * D_];   // Q [bh][s][d]
__device__ __align__(16) __half g_k0[(size_t)BH_ * S_ * D_];   // K [bh][s][d]
__device__ __align__(16) __half g_v0[(size_t)BH_ * D_ * S_];   // V [bh][d][s]
__device__ __align__(16) __half g_c0[(size_t)NROWS * HD_];  // ctx (fp16)

// ---------------------------------------------------------------------------
// PTX helpers: arch-agnostic tensor path (mma.sync / ldmatrix / cp.async).
// tcgen05 is NOT usable: the harness PTX stage targets compute_103 (no 'a').
// ---------------------------------------------------------------------------
__device__ __forceinline__ uint32_t smem_u32(const void* p) {
    return (uint32_t)__cvta_generic_to_shared(p);
}

__device__ __forceinline__ void cp16(uint32_t saddr, const void* g) {
    asm volatile("cp.async.cg.shared.global [%0], [%1], 16;"
                 :: "r"(saddr), "l"(g));
}
#define CP_COMMIT() asm volatile("cp.async.commit_group;" ::: "memory")
#define CP_WAIT(n)  asm volatile("cp.async.wait_group %0;" :: "n"(n) : "memory")

__device__ __forceinline__ void ldsm4(uint32_t* r, uint32_t addr) {
    asm volatile("ldmatrix.sync.aligned.m8n8.x4.shared.b16 {%0,%1,%2,%3}, [%4];"
                 : "=r"(r[0]), "=r"(r[1]), "=r"(r[2]), "=r"(r[3]) : "r"(addr));
}

__device__ __forceinline__ void mma_f16(float* c, const uint32_t* a,
                                        const uint32_t* b) {
    asm volatile(
        "mma.sync.aligned.m16n8k16.row.col.f32.f16.f16.f32 "
        "{%0,%1,%2,%3}, {%4,%5,%6,%7}, {%8,%9}, {%0,%1,%2,%3};"
        : "+f"(c[0]), "+f"(c[1]), "+f"(c[2]), "+f"(c[3])
        : "r"(a[0]), "r"(a[1]), "r"(a[2]), "r"(a[3]), "r"(b[0]), "r"(b[1]));
}

// Shared tile layout: [rows x 64] fp16, 128-byte rows (8 x 16B chunks),
// chunk' = c ^ (r & 7). Conflict-free for cp.async fill and ldmatrix reads.
__device__ __forceinline__ uint32_t s128(int r, int c) {
    return (uint32_t)(r * 128 + ((c ^ (r & 7)) << 4));
}

// plain fp16 pack of a float pair
__device__ __forceinline__ uint32_t pack2h(float x0, float x1) {
    __half2 h;
    h.x = __float2half_rn(x0);
    h.y = __float2half_rn(x1);
    return *(uint32_t*)&h;
}

// ---------------------------------------------------------------------------
// Kernel 1 (fused preprocessing): one launch covering
//   blocks [0, 4096):          LayerNorm -> fp16 activations
//   blocks [4096, 7168):       w_qkv transpose -> fp16  (96 x 32 tiles)
//   blocks [7168, 8192):       w_out transpose -> fp16  (32 x 32 tiles)
// ---------------------------------------------------------------------------
__device__ __forceinline__ void wtrans_body(float* sh,
                                            const float* __restrict__ W,
                                            __half* __restrict__ o,
                                            int K, int N, int gx, int gy) {
    float (*tile)[33] = (float(*)[33])sh;
    const int bx = gx * 32;        // n base
    const int by = gy * 32;        // k base
    const int tx = threadIdx.x & 31;
    const int ty = threadIdx.x >> 5;

    #pragma unroll
    for (int i = 0; i < 32; i += 8)
        tile[ty + i][tx] = W[(size_t)(by + ty + i) * N + bx + tx];
    __syncthreads();
    #pragma unroll
    for (int i = 0; i < 32; i += 8) {
        float v = tile[tx][ty + i];
        o[(size_t)(bx + ty + i) * K + by + tx] = __float2half_rn(v);
    }
}

__global__ __launch_bounds__(256)
void pre_kernel(const float* __restrict__ x,
                const float* __restrict__ scale,
                __half* __restrict__ a0,
                const float* __restrict__ wqkv,
                __half* __restrict__ wq,
                const float* __restrict__ wout,
                __half* __restrict__ wo) {
    __shared__ float sh[32 * 33];
    const int bid = blockIdx.x;

    if (bid >= NROWS) {
        if (bid < NROWS + 3072) {
            int idx = bid - NROWS;
            wtrans_body(sh, wqkv, wq, E_, Q3_, idx % 96, idx / 96);
        } else {
            int idx = bid - NROWS - 3072;
            wtrans_body(sh, wout, wo, HD_, E_, idx % 32, idx / 32);
        }
        return;
    }

    // ---- LayerNorm -> fp16 ----
    float* red_s  = sh;
    float* red_ss = sh + 8;
    const int row = bid;
    const int t   = threadIdx.x;
    const float* xr = x + (size_t)row * E_;

    float4 v = *(const float4*)&xr[t * 4];
    float s  = v.x + v.y + v.z + v.w;
    float ss = v.x * v.x + v.y * v.y + v.z * v.z + v.w * v.w;

    #pragma unroll
    for (int o = 16; o; o >>= 1) {
        s  += __shfl_xor_sync(0xFFFFFFFFu, s,  o);
        ss += __shfl_xor_sync(0xFFFFFFFFu, ss, o);
    }
    if ((t & 31) == 0) { red_s[t >> 5] = s; red_ss[t >> 5] = ss; }
    __syncthreads();
    if (t < 32) {
        float s2  = (t < 8) ? red_s[t]  : 0.f;
        float ss2 = (t < 8) ? red_ss[t] : 0.f;
        #pragma unroll
        for (int o = 4; o; o >>= 1) {
            s2  += __shfl_xor_sync(0xFFFFFFFFu, s2,  o);
            ss2 += __shfl_xor_sync(0xFFFFFFFFu, ss2, o);
        }
        if (t == 0) { red_s[0] = s2; red_ss[0] = ss2; }
    }
    __syncthreads();

    const float inv_e = 1.f / (float)E_;
    float mu  = red_s[0] * inv_e;
    float var = red_ss[0] * inv_e - mu * mu;
    float r   = rsqrtf(var + 1e-6f);

    float4 sc = *(const float4*)&scale[t * 4];
    const size_t base = (size_t)row * E_ + t * 4;
    *(uint32_t*)&a0[base]     = pack2h((v.x - mu) * r * sc.x,
                                       (v.y - mu) * r * sc.y);
    *(uint32_t*)&a0[base + 2] = pack2h((v.z - mu) * r * sc.z,
                                       (v.w - mu) * r * sc.w);
}

// ---------------------------------------------------------------------------
// Kernel 2: persistent plain-fp16 HMMA GEMM: C = A*B (A [M,K], B [N,K] K-major).
// Grid = min(nTiles, 296); CTA p owns tiles p, p+grid, ... Flat chunk index
// g = tileIdx*16 + ch drives ONE continuous 3-stage cp.async pipeline that
// never drains across tile boundaries: the epilogue of tile t overlaps with
// the prefetch (and compute) of tile t+1. One barrier per 64-wide K-chunk.
// MODE 0: fp32 C store. MODE 1 (QKV): scatter to single-fp16 attention
// operands — Q/K [bh][s][d], V [bh][d][s] (transposed).  K is always 1024
// here (NCH = 16 chunks per tile).
// ---------------------------------------------------------------------------
#define GBM 128
#define GBN 128
#define GBK 64
#define TILE_B   16384                // 128 rows x 64 fp16 (128-B rows)
#define STAGE_B  (2 * TILE_B)         // A | B
#define GSM_TOTAL (3 * STAGE_B)       // 96 KB, 3 stages

template <int MODE>
__global__ __launch_bounds__(256, 2)
void mma_gemm_kernel(const __half* __restrict__ A,
                     const __half* __restrict__ B,
                     float* __restrict__ C,
                     __half* __restrict__ oQ0,
                     __half* __restrict__ oK0, __half* __restrict__ oV0,
                     int N, int K) {
    extern __shared__ char sm[];
    const uint32_t smb = smem_u32(sm);

    const int tid  = threadIdx.x;
    const int lane = tid & 31;
    const int wid  = tid >> 5;
    const int wm   = wid & 3;
    const int wn   = wid >> 2;

    const int cta  = blockIdx.x;
    const int nCTA = gridDim.x;
    const int nTx  = N >> 7;                    // tiles along N
    const int nTiles = nTx * (NROWS >> 7);      // M fixed at 4096
    const int myTiles = (nTiles - 1 - cta) / nCTA + 1;
    const int G = myTiles * 16;                 // flat chunks (16 per tile)

    float acc[2][8][4];
    #pragma unroll
    for (int i = 0; i < 2; i++)
        #pragma unroll
        for (int j = 0; j < 8; j++)
            #pragma unroll
            for (int q = 0; q < 4; q++) acc[i][j][q] = 0.f;

    // Per-thread load coords: 4 chunks per tile per stage (1024 chunks/tile)
    const int lr[4] = { (tid + 0) >> 3, (tid + 256) >> 3,
                        (tid + 512) >> 3, (tid + 768) >> 3 };
    const int lc[4] = { (tid + 0) & 7, (tid + 256) & 7,
                        (tid + 512) & 7, (tid + 768) & 7 };
    uint32_t lso[4];
    #pragma unroll
    for (int i = 0; i < 4; i++) lso[i] = s128(lr[i], lc[i]);

    // Issue all cp.async for flat chunk g into stage g%3, then commit.
    auto issue = [&](int g) {
        const int t    = cta + (g >> 4) * nCTA;
        const int bRow = (t / nTx) << 7;
        const int bCol = (t % nTx) << 7;
        const int kb   = (g & 15) << 6;
        const uint32_t sb = smb + (g % 3) * STAGE_B;
        #pragma unroll
        for (int i = 0; i < 4; i++) {
            cp16(sb + lso[i],
                 A + (size_t)(bRow + lr[i]) * K + kb + lc[i] * 8);
            cp16(sb + TILE_B + lso[i],
                 B + (size_t)(bCol + lr[i]) * K + kb + lc[i] * 8);
        }
        CP_COMMIT();
    };

    // Prologue: chunks 0 and 1 (stages 0, 1)
    issue(0);
    if (G > 1) issue(1);

    const int rA = wm * 32 + (lane & 15);
    const int cAbase = lane >> 4;
    const int rB = wn * 64 + (lane & 7) + ((lane >> 4) << 3);
    const int cBbase = (lane >> 3) & 1;

    for (int g = 0; g < G; g++) {
        if (g + 1 < G) { CP_WAIT(1); } else { CP_WAIT(0); }
        __syncthreads();    // publish stage g + prove compute g-1 done

        if (g + 2 < G) issue(g + 2);

        const uint32_t sA = smb + (g % 3) * STAGE_B;
        const uint32_t sB = sA + TILE_B;

        #pragma unroll
        for (int ks = 0; ks < 4; ks++) {
            const int cA = ks * 2 + cAbase;
            const int cB = ks * 2 + cBbase;
            uint32_t af[2][4];
            #pragma unroll
            for (int fm = 0; fm < 2; fm++)
                ldsm4(af[fm], sA + s128(rA + fm * 16, cA));
            uint32_t bf[4][4];
            #pragma unroll
            for (int p = 0; p < 4; p++)
                ldsm4(bf[p], sB + s128(rB + p * 16, cB));
            #pragma unroll
            for (int fm = 0; fm < 2; fm++)
                #pragma unroll
                for (int fn = 0; fn < 8; fn++)
                    mma_f16(acc[fm][fn], af[fm], &bf[fn >> 1][(fn & 1) * 2]);
        }

        if ((g & 15) == 15) {
            // ---- Tile epilogue (overlaps with prefetch of next tile) ----
            const int t    = cta + (g >> 4) * nCTA;
            const int blockRow = (t / nTx) << 7;
            const int blockCol = (t % nTx) << 7;

            if (MODE == 0) {
                #pragma unroll
                for (int fm = 0; fm < 2; fm++) {
                    const int rr = blockRow + wm * 32 + fm * 16 + (lane >> 2);
                    #pragma unroll
                    for (int fn = 0; fn < 8; fn++) {
                        const int cc = blockCol + wn * 64 + fn * 8 + (lane & 3) * 2;
                        *(float2*)&C[(size_t)rr * N + cc] =
                            make_float2(acc[fm][fn][0], acc[fm][fn][1]);
                        *(float2*)&C[(size_t)(rr + 8) * N + cc] =
                            make_float2(acc[fm][fn][2], acc[fm][fn][3]);
                    }
                }
            } else {
                const int part = blockCol >> 10;   // 0=q, 1=k, 2=v
                #pragma unroll
                for (int fm = 0; fm < 2; fm++) {
                    const int rbase = blockRow + wm * 32 + fm * 16 + (lane >> 2);
                    #pragma unroll
                    for (int fn = 0; fn < 8; fn++) {
                        const int cc = blockCol + wn * 64 + fn * 8 + (lane & 3) * 2;
                        const int h = (cc >> 6) & 15;
                        const int d = cc & 63;
                        #pragma unroll
                        for (int hf = 0; hf < 2; hf++) {
                            const int rr = rbase + hf * 8;
                            const int s = rr >> 1, b = rr & 1;
                            const int bh = b * 16 + h;
                            const float x0 = acc[fm][fn][hf * 2];
                            const float x1 = acc[fm][fn][hf * 2 + 1];
                            if (part == 0) {
                                size_t off = ((size_t)bh * S_ + s) * D_ + d;
                                *(uint32_t*)&oQ0[off] = pack2h(x0, x1);
                            } else if (part == 1) {
                                size_t off = ((size_t)bh * S_ + s) * D_ + d;
                                *(uint32_t*)&oK0[off] = pack2h(x0, x1);
                            } else {
                                size_t offa = ((size_t)bh * D_ + d) * S_ + s;
                                size_t offb = ((size_t)bh * D_ + d + 1) * S_ + s;
                                oV0[offa] = __float2half_rn(x0);
                                oV0[offb] = __float2half_rn(x1);
                            }
                        }
                    }
                }
            }
            // Reset accumulators for the next tile
            #pragma unroll
            for (int i = 0; i < 2; i++)
                #pragma unroll
                for (int j = 0; j < 8; j++)
                    #pragma unroll
                    for (int q = 0; q < 4; q++) acc[i][j][q] = 0.f;
        }
        // no trailing barrier: next iteration's barrier protects stage reuse
    }
}

// ---------------------------------------------------------------------------
// Kernel 3: fp16 tensor-core flash attention, single product per stage.
// Grid (S/128, 32 bh). 256 threads = 8 warps; warp w owns q rows [16w,16w+16).
// QK^T = Q*K.  PV = P*V (P packed from C-frags).
// K/V tiles (16 KB/stage) double-buffered via cp.async; single barrier/tile.
// Epilogue: single-fp16 ctx for the plain-fp16 out-projection.
// ---------------------------------------------------------------------------
#define AQT 128
#define ASM_STAGE 16384     // K | V, each 8 KB
#define ASM_Q 32768
#define ASM_TOTAL 49152     // 48 KB

__global__ __launch_bounds__(256)
void attn_mma_kernel(const __half* __restrict__ Qh,
                     const __half* __restrict__ Kh,
                     const __half* __restrict__ Vh,
                     __half* __restrict__ c0) {
    extern __shared__ char sm[];
    const uint32_t smb = smem_u32(sm);
    const int tid  = threadIdx.x;
    const int lane = tid & 31;
    const int wq   = tid >> 5;               // 0..7
    const int bh   = blockIdx.y;             // b*16 + h
    const int qb   = blockIdx.x * AQT;
    const size_t kbase = (size_t)bh * S_ * D_;   // Q/K [bh][s][d]
    const size_t vbase = (size_t)bh * D_ * S_;   // V  [bh][d][s]

    // Stage Q tile [128][64] fp16 (group 0)
    #pragma unroll
    for (int i = 0; i < 4; i++) {
        int idx = tid + i * 256;             // 0..1023
        int r = idx >> 3, c = idx & 7;
        cp16(smb + ASM_Q + s128(r, c),
             Qh + kbase + (size_t)(qb + r) * D_ + c * 8);
    }
    CP_COMMIT();
    // Key tile 0 (group 1): K [64][64], V [64][64]
    #pragma unroll
    for (int i = 0; i < 2; i++) {
        int idx = tid + i * 256;             // 0..511
        int r = idx >> 3, c = idx & 7;
        uint32_t so = s128(r, c);
        cp16(smb + so,        Kh + kbase + (size_t)r * D_ + c * 8);
        cp16(smb + 8192 + so, Vh + vbase + (size_t)r * S_ + c * 8);
    }
    CP_COMMIT();
    CP_WAIT(1);        // Q resident (tile 0 may still be in flight)
    __syncthreads();

    // Q fragments (held for the whole kernel)
    uint32_t qf[4][4];
    {
        const int rA = wq * 16 + (lane & 15);
        const int cA = lane >> 4;
        #pragma unroll
        for (int t = 0; t < 4; t++)
            ldsm4(qf[t], smb + ASM_Q + s128(rA, t * 2 + cA));
    }

    float acc[8][4];
    #pragma unroll
    for (int j = 0; j < 8; j++)
        #pragma unroll
        for (int q = 0; q < 4; q++) acc[j][q] = 0.f;
    float mrow[2] = {-1e30f, -1e30f};
    float lrow[2] = {0.f, 0.f};

    const int rB = (lane & 7) + ((lane >> 4) << 3);
    const int cB = (lane >> 3) & 1;
    const int NKT = S_ / 64;                 // 32 key tiles

    for (int kc = 0; kc < NKT; kc++) {
        CP_WAIT(0);         // stage kc ready (own groups)
        __syncthreads();    // publish stage kc + prove compute kc-1 done

        if (kc + 1 < NKT) {
            const uint32_t sb = smb + ((kc + 1) & 1) * ASM_STAGE;
            #pragma unroll
            for (int i = 0; i < 2; i++) {
                int idx = tid + i * 256;
                int r = idx >> 3, c = idx & 7;
                uint32_t so = s128(r, c);
                cp16(sb + so,
                     Kh + kbase + (size_t)((kc + 1) * 64 + r) * D_ + c * 8);
                cp16(sb + 8192 + so,
                     Vh + vbase + (size_t)r * S_ + (kc + 1) * 64 + c * 8);
            }
            CP_COMMIT();
        }
        const uint32_t sb = smb + (kc & 1) * ASM_STAGE;

        // ---- Scores: s[16q x 64k] over d=64, single product ----
        float sc[8][4];
        #pragma unroll
        for (int j = 0; j < 8; j++)
            #pragma unroll
            for (int q = 0; q < 4; q++) sc[j][q] = 0.f;

        #pragma unroll
        for (int t = 0; t < 4; t++) {
            #pragma unroll
            for (int jj = 0; jj < 4; jj++) {
                uint32_t k0f[4];
                ldsm4(k0f, sb + s128(jj * 16 + rB, t * 2 + cB));
                mma_f16(sc[2 * jj],     qf[t], &k0f[0]);
                mma_f16(sc[2 * jj + 1], qf[t], &k0f[2]);
            }
        }

        // ---- Online softmax on fragments (rows r=lane>>2 and r+8) ----
        #pragma unroll
        for (int h2 = 0; h2 < 2; h2++) {
            float rm = sc[0][2 * h2];
            #pragma unroll
            for (int j = 0; j < 8; j++) {
                rm = fmaxf(rm, sc[j][2 * h2]);
                rm = fmaxf(rm, sc[j][2 * h2 + 1]);
            }
            rm = fmaxf(rm, __shfl_xor_sync(0xFFFFFFFFu, rm, 1));
            rm = fmaxf(rm, __shfl_xor_sync(0xFFFFFFFFu, rm, 2));
            float mnew = fmaxf(mrow[h2], rm);
            float al   = __expf(mrow[h2] - mnew);
            mrow[h2] = mnew;
            float rs = 0.f;
            #pragma unroll
            for (int j = 0; j < 8; j++) {
                float p0 = __expf(sc[j][2 * h2]     - mnew);
                float p1 = __expf(sc[j][2 * h2 + 1] - mnew);
                sc[j][2 * h2]     = p0;
                sc[j][2 * h2 + 1] = p1;
                rs += p0 + p1;
            }
            rs += __shfl_xor_sync(0xFFFFFFFFu, rs, 1);
            rs += __shfl_xor_sync(0xFFFFFFFFu, rs, 2);
            lrow[h2] = lrow[h2] * al + rs;
            #pragma unroll
            for (int j = 0; j < 8; j++) {
                acc[j][2 * h2]     *= al;
                acc[j][2 * h2 + 1] *= al;
            }
        }

        // ---- PV: ctx += P * V, single product; P packed from C-frags ----
        #pragma unroll
        for (int t2 = 0; t2 < 4; t2++) {
            uint32_t ah[4];
            ah[0] = pack2h(sc[2 * t2][0],     sc[2 * t2][1]);
            ah[1] = pack2h(sc[2 * t2][2],     sc[2 * t2][3]);
            ah[2] = pack2h(sc[2 * t2 + 1][0], sc[2 * t2 + 1][1]);
            ah[3] = pack2h(sc[2 * t2 + 1][2], sc[2 * t2 + 1][3]);
            #pragma unroll
            for (int jj = 0; jj < 4; jj++) {
                uint32_t v0f[4];
                ldsm4(v0f, sb + 8192 + s128(jj * 16 + rB, t2 * 2 + cB));
                mma_f16(acc[2 * jj],     ah, &v0f[0]);
                mma_f16(acc[2 * jj + 1], ah, &v0f[2]);
            }
        }
        // no trailing barrier: next iteration's barrier protects stage reuse
    }

    // ---- Epilogue: normalize, single fp16 into c0 [NROWS][HD] ----
    const int b = bh >> 4, h = bh & 15;
    const float inv0 = 1.f / lrow[0];
    const float inv1 = 1.f / lrow[1];
    const int r  = lane >> 2;
    const int c2 = (lane & 3) * 2;
    #pragma unroll
    for (int j = 0; j < 8; j++) {
        const int d = j * 8 + c2;
        const int qg = qb + wq * 16 + r;
        size_t off0 = (size_t)(qg * 2 + b) * HD_ + h * 64 + d;
        size_t off1 = (size_t)((qg + 8) * 2 + b) * HD_ + h * 64 + d;
        *(uint32_t*)&c0[off0] = pack2h(acc[j][0] * inv0, acc[j][1] * inv0);
        *(uint32_t*)&c0[off1] = pack2h(acc[j][2] * inv1, acc[j][3] * inv1);
    }
}

// ---------------------------------------------------------------------------
// kernel_launch
// ---------------------------------------------------------------------------
extern "C" void kernel_launch(void* const* d_in, const int* in_sizes, int n_in,
                              void* d_out, int out_size) {
    const float* x        = (const float*)d_in[0];   // [S,B,E]
    const float* ln_scale = (const float*)d_in[1];   // [E]
    const float* w_qkv    = (const float*)d_in[2];   // [E, 3*H*D]
    const float* w_out    = (const float*)d_in[3];   // [H*D, E]
    float* out = (float*)d_out;                      // [S,B,E]

    __half *p_a0, *p_wq, *p_wo;
    __half *pQ0, *pK0, *pV0, *p_c0;
    cudaGetSymbolAddress((void**)&p_a0, g_a0);
    cudaGetSymbolAddress((void**)&p_wq, g_wq);
    cudaGetSymbolAddress((void**)&p_wo, g_wo);
    cudaGetSymbolAddress((void**)&pQ0,  g_q0);
    cudaGetSymbolAddress((void**)&pK0,  g_k0);
    cudaGetSymbolAddress((void**)&pV0,  g_v0);
    cudaGetSymbolAddress((void**)&p_c0, g_c0);

    cudaFuncSetAttribute(mma_gemm_kernel<0>,
                         cudaFuncAttributeMaxDynamicSharedMemorySize, GSM_TOTAL);
    cudaFuncSetAttribute(mma_gemm_kernel<1>,
                         cudaFuncAttributeMaxDynamicSharedMemorySize, GSM_TOTAL);
    cudaFuncSetAttribute(attn_mma_kernel,
                         cudaFuncAttributeMaxDynamicSharedMemorySize, ASM_TOTAL);

    // 1. Fused preprocessing: LayerNorm->fp16 and both weight transposes
    pre_kernel<<<NROWS + 3072 + 1024, 256>>>(
        x, ln_scale, p_a0, w_qkv, p_wq, w_out, p_wo);

    // 2. QKV projection (persistent grid): 768 tiles on 296 CTAs
    {
        const int nTiles = (Q3_ / GBN) * (NROWS / GBM);   // 768
        const int grid = nTiles < NCTA_FULL ? nTiles : NCTA_FULL;
        mma_gemm_kernel<1><<<grid, 256, GSM_TOTAL>>>(
            p_a0, p_wq, nullptr, pQ0, pK0, pV0, Q3_, E_);
    }

    // 3. fp16 tensor-core flash attention
    attn_mma_kernel<<<dim3(S_ / AQT, BH_), 256, ASM_TOTAL>>>(
        pQ0, pK0, pV0, p_c0);

    // 4. Output projection (persistent grid): 256 tiles
    {
        const int nTiles = (E_ / GBN) * (NROWS / GBM);    // 256
        const int grid = nTiles < NCTA_FULL ? nTiles : NCTA_FULL;
        mma_gemm_kernel<0><<<grid, 256, GSM_TOTAL>>>(
            p_c0, p_wo, out, nullptr, nullptr, nullptr, E_, HD_);
    }
}

// round 17
// speedup vs baseline: 1.0435x; 1.0435x over previous
#include <cuda_runtime.h>
#include <cuda_fp16.h>
#include <cstdint>

// Problem constants
#define S_    2048
#define B_    2
#define E_    1024
#define H_    16
#define D_    64
#define HD_   1024
#define Q3_   3072
#define NROWS (S_ * B_)   // 4096 rows, row index = s*B + b
#define BH_   32          // b*16 + h

// ---------------------------------------------------------------------------
// Scratch (device globals: cudaMalloc is forbidden by the harness)
// ---------------------------------------------------------------------------
__device__ __align__(16) __half g_a0[(size_t)NROWS * E_];   // LN out (fp16)
__device__ __align__(16) __half g_wq[(size_t)Q3_ * E_];     // w_qkv^T fp16 [3072,1024]
__device__ __align__(16) __half g_wo[(size_t)E_ * HD_];     // w_out^T fp16 [1024,1024]
// Attention operands (single fp16), written by the QKV GEMM epilogue:
__device__ __align__(16) __half g_q0[(size_t)BH_ * S_ * D_];   // Q [bh][s][d]
__device__ __align__(16) __half g_k0[(size_t)BH_ * S_ * D_];   // K [bh][s][d]
__device__ __align__(16) __half g_v0[(size_t)BH_ * D_ * S_];   // V [bh][d][s]
__device__ __align__(16) __half g_c0[(size_t)NROWS * HD_];  // ctx (fp16)

// ---------------------------------------------------------------------------
// PTX helpers: arch-agnostic tensor path (mma.sync / ldmatrix / cp.async).
// tcgen05 is NOT usable: the harness PTX stage targets compute_103 (no 'a').
// ---------------------------------------------------------------------------
__device__ __forceinline__ uint32_t smem_u32(const void* p) {
    return (uint32_t)__cvta_generic_to_shared(p);
}

__device__ __forceinline__ void cp16(uint32_t saddr, const void* g) {
    asm volatile("cp.async.cg.shared.global [%0], [%1], 16;"
                 :: "r"(saddr), "l"(g));
}
#define CP_COMMIT() asm volatile("cp.async.commit_group;" ::: "memory")
#define CP_WAIT(n)  asm volatile("cp.async.wait_group %0;" :: "n"(n) : "memory")

__device__ __forceinline__ void ldsm4(uint32_t* r, uint32_t addr) {
    asm volatile("ldmatrix.sync.aligned.m8n8.x4.shared.b16 {%0,%1,%2,%3}, [%4];"
                 : "=r"(r[0]), "=r"(r[1]), "=r"(r[2]), "=r"(r[3]) : "r"(addr));
}

__device__ __forceinline__ void mma_f16(float* c, const uint32_t* a,
                                        const uint32_t* b) {
    asm volatile(
        "mma.sync.aligned.m16n8k16.row.col.f32.f16.f16.f32 "
        "{%0,%1,%2,%3}, {%4,%5,%6,%7}, {%8,%9}, {%0,%1,%2,%3};"
        : "+f"(c[0]), "+f"(c[1]), "+f"(c[2]), "+f"(c[3])
        : "r"(a[0]), "r"(a[1]), "r"(a[2]), "r"(a[3]), "r"(b[0]), "r"(b[1]));
}

// Shared tile layout: [rows x 64] fp16, 128-byte rows (8 x 16B chunks),
// chunk' = c ^ (r & 7). Conflict-free for cp.async fill and ldmatrix reads.
__device__ __forceinline__ uint32_t s128(int r, int c) {
    return (uint32_t)(r * 128 + ((c ^ (r & 7)) << 4));
}

// plain fp16 pack of a float pair
__device__ __forceinline__ uint32_t pack2h(float x0, float x1) {
    __half2 h;
    h.x = __float2half_rn(x0);
    h.y = __float2half_rn(x1);
    return *(uint32_t*)&h;
}

// ---------------------------------------------------------------------------
// Kernel 1 (fused preprocessing): one launch covering
//   blocks [0, 4096):          LayerNorm -> fp16 activations
//   blocks [4096, 7168):       w_qkv transpose -> fp16  (96 x 32 tiles)
//   blocks [7168, 8192):       w_out transpose -> fp16  (32 x 32 tiles)
// ---------------------------------------------------------------------------
__device__ __forceinline__ void wtrans_body(float* sh,
                                            const float* __restrict__ W,
                                            __half* __restrict__ o,
                                            int K, int N, int gx, int gy) {
    float (*tile)[33] = (float(*)[33])sh;
    const int bx = gx * 32;        // n base
    const int by = gy * 32;        // k base
    const int tx = threadIdx.x & 31;
    const int ty = threadIdx.x >> 5;

    #pragma unroll
    for (int i = 0; i < 32; i += 8)
        tile[ty + i][tx] = W[(size_t)(by + ty + i) * N + bx + tx];
    __syncthreads();
    #pragma unroll
    for (int i = 0; i < 32; i += 8) {
        float v = tile[tx][ty + i];
        o[(size_t)(bx + ty + i) * K + by + tx] = __float2half_rn(v);
    }
}

__global__ __launch_bounds__(256)
void pre_kernel(const float* __restrict__ x,
                const float* __restrict__ scale,
                __half* __restrict__ a0,
                const float* __restrict__ wqkv,
                __half* __restrict__ wq,
                const float* __restrict__ wout,
                __half* __restrict__ wo) {
    __shared__ float sh[32 * 33];
    const int bid = blockIdx.x;

    if (bid >= NROWS) {
        if (bid < NROWS + 3072) {
            int idx = bid - NROWS;
            wtrans_body(sh, wqkv, wq, E_, Q3_, idx % 96, idx / 96);
        } else {
            int idx = bid - NROWS - 3072;
            wtrans_body(sh, wout, wo, HD_, E_, idx % 32, idx / 32);
        }
        return;
    }

    // ---- LayerNorm -> fp16 ----
    float* red_s  = sh;
    float* red_ss = sh + 8;
    const int row = bid;
    const int t   = threadIdx.x;
    const float* xr = x + (size_t)row * E_;

    float4 v = *(const float4*)&xr[t * 4];
    float s  = v.x + v.y + v.z + v.w;
    float ss = v.x * v.x + v.y * v.y + v.z * v.z + v.w * v.w;

    #pragma unroll
    for (int o = 16; o; o >>= 1) {
        s  += __shfl_xor_sync(0xFFFFFFFFu, s,  o);
        ss += __shfl_xor_sync(0xFFFFFFFFu, ss, o);
    }
    if ((t & 31) == 0) { red_s[t >> 5] = s; red_ss[t >> 5] = ss; }
    __syncthreads();
    if (t < 32) {
        float s2  = (t < 8) ? red_s[t]  : 0.f;
        float ss2 = (t < 8) ? red_ss[t] : 0.f;
        #pragma unroll
        for (int o = 4; o; o >>= 1) {
            s2  += __shfl_xor_sync(0xFFFFFFFFu, s2,  o);
            ss2 += __shfl_xor_sync(0xFFFFFFFFu, ss2, o);
        }
        if (t == 0) { red_s[0] = s2; red_ss[0] = ss2; }
    }
    __syncthreads();

    const float inv_e = 1.f / (float)E_;
    float mu  = red_s[0] * inv_e;
    float var = red_ss[0] * inv_e - mu * mu;
    float r   = rsqrtf(var + 1e-6f);

    float4 sc = *(const float4*)&scale[t * 4];
    const size_t base = (size_t)row * E_ + t * 4;
    *(uint32_t*)&a0[base]     = pack2h((v.x - mu) * r * sc.x,
                                       (v.y - mu) * r * sc.y);
    *(uint32_t*)&a0[base + 2] = pack2h((v.z - mu) * r * sc.z,
                                       (v.w - mu) * r * sc.w);
}

// ---------------------------------------------------------------------------
// Kernel 2: plain fp16 HMMA GEMM: C = A*B  (A [M,K] fp16, B [N,K] K-major).
// (R14 structure — the persistent-grid variant regressed and was reverted.)
// GBK=64 K-chunks: 4 ks-iterations (64 MMAs/warp) per single barrier.
// 3-stage cp.async pipeline (2 tiles x 16KB per stage = 96 KB total).
// MODE 0: fp32 C store. MODE 1 (QKV): scatter to single-fp16 attention
// operands — Q/K [bh][s][d], V [bh][d][s] (transposed).
// ---------------------------------------------------------------------------
#define GBM 128
#define GBN 128
#define GBK 64
#define TILE_B   16384                // 128 rows x 64 fp16 (128-B rows)
#define STAGE_B  (2 * TILE_B)         // A | B
#define GSM_TOTAL (3 * STAGE_B)       // 96 KB, 3 stages

template <int MODE>
__global__ __launch_bounds__(256, 2)
void mma_gemm_kernel(const __half* __restrict__ A,
                     const __half* __restrict__ B,
                     float* __restrict__ C,
                     __half* __restrict__ oQ0,
                     __half* __restrict__ oK0, __half* __restrict__ oV0,
                     int N, int K) {
    extern __shared__ char sm[];
    const uint32_t smb = smem_u32(sm);

    const int tid  = threadIdx.x;
    const int lane = tid & 31;
    const int wid  = tid >> 5;
    const int wm   = wid & 3;
    const int wn   = wid >> 2;
    const int blockRow = blockIdx.y * GBM;
    const int blockCol = blockIdx.x * GBN;

    float acc[2][8][4];
    #pragma unroll
    for (int i = 0; i < 2; i++)
        #pragma unroll
        for (int j = 0; j < 8; j++)
            #pragma unroll
            for (int q = 0; q < 4; q++) acc[i][j][q] = 0.f;

    // Per-thread load coords: 4 chunks per tile per stage (1024 chunks/tile)
    const int lr[4] = { (tid + 0) >> 3, (tid + 256) >> 3,
                        (tid + 512) >> 3, (tid + 768) >> 3 };
    const int lc[4] = { (tid + 0) & 7, (tid + 256) & 7,
                        (tid + 512) & 7, (tid + 768) & 7 };
    uint32_t lso[4];
    #pragma unroll
    for (int i = 0; i < 4; i++) lso[i] = s128(lr[i], lc[i]);

    const int NCH = K / GBK;               // 16

    // Prologue: stages 0 and 1 (chunks 0 and 1), separate commit groups
    #pragma unroll
    for (int st = 0; st < 2; st++) {
        const uint32_t sb = smb + st * STAGE_B;
        const int kb = st * GBK;
        #pragma unroll
        for (int i = 0; i < 4; i++) {
            cp16(sb + lso[i],
                 A + (size_t)(blockRow + lr[i]) * K + kb + lc[i] * 8);
            cp16(sb + TILE_B + lso[i],
                 B + (size_t)(blockCol + lr[i]) * K + kb + lc[i] * 8);
        }
        CP_COMMIT();
    }

    const int rA = wm * 32 + (lane & 15);
    const int cAbase = lane >> 4;
    const int rB = wn * 64 + (lane & 7) + ((lane >> 4) << 3);
    const int cBbase = (lane >> 3) & 1;

    for (int ch = 0; ch < NCH; ch++) {
        if (ch + 1 < NCH) { CP_WAIT(1); } else { CP_WAIT(0); }
        __syncthreads();    // publish stage ch + prove compute ch-1 done

        if (ch + 2 < NCH) {
            const uint32_t sb = smb + ((ch + 2) % 3) * STAGE_B;
            const int kb = (ch + 2) * GBK;
            #pragma unroll
            for (int i = 0; i < 4; i++) {
                cp16(sb + lso[i],
                     A + (size_t)(blockRow + lr[i]) * K + kb + lc[i] * 8);
                cp16(sb + TILE_B + lso[i],
                     B + (size_t)(blockCol + lr[i]) * K + kb + lc[i] * 8);
            }
            CP_COMMIT();
        }

        const uint32_t sA = smb + (ch % 3) * STAGE_B;
        const uint32_t sB = sA + TILE_B;

        #pragma unroll
        for (int ks = 0; ks < 4; ks++) {
            const int cA = ks * 2 + cAbase;
            const int cB = ks * 2 + cBbase;
            uint32_t af[2][4];
            #pragma unroll
            for (int fm = 0; fm < 2; fm++)
                ldsm4(af[fm], sA + s128(rA + fm * 16, cA));
            uint32_t bf[4][4];
            #pragma unroll
            for (int p = 0; p < 4; p++)
                ldsm4(bf[p], sB + s128(rB + p * 16, cB));
            #pragma unroll
            for (int fm = 0; fm < 2; fm++)
                #pragma unroll
                for (int fn = 0; fn < 8; fn++)
                    mma_f16(acc[fm][fn], af[fm], &bf[fn >> 1][(fn & 1) * 2]);
        }
        // no trailing barrier: next iteration's barrier protects stage reuse
    }

    if (MODE == 0) {
        // fp32 C store
        #pragma unroll
        for (int fm = 0; fm < 2; fm++) {
            const int rr = blockRow + wm * 32 + fm * 16 + (lane >> 2);
            #pragma unroll
            for (int fn = 0; fn < 8; fn++) {
                const int cc = blockCol + wn * 64 + fn * 8 + (lane & 3) * 2;
                *(float2*)&C[(size_t)rr * N + cc] =
                    make_float2(acc[fm][fn][0], acc[fm][fn][1]);
                *(float2*)&C[(size_t)(rr + 8) * N + cc] =
                    make_float2(acc[fm][fn][2], acc[fm][fn][3]);
            }
        }
    } else {
        // QKV scatter: part uniform per CTA (1024 | 128*gridX boundaries)
        const int part = blockCol >> 10;   // 0=q, 1=k, 2=v
        #pragma unroll
        for (int fm = 0; fm < 2; fm++) {
            const int rbase = blockRow + wm * 32 + fm * 16 + (lane >> 2);
            #pragma unroll
            for (int fn = 0; fn < 8; fn++) {
                const int cc = blockCol + wn * 64 + fn * 8 + (lane & 3) * 2;
                const int h = (cc >> 6) & 15;
                const int d = cc & 63;
                #pragma unroll
                for (int hf = 0; hf < 2; hf++) {
                    const int rr = rbase + hf * 8;
                    const int s = rr >> 1, b = rr & 1;
                    const int bh = b * 16 + h;
                    const float x0 = acc[fm][fn][hf * 2];
                    const float x1 = acc[fm][fn][hf * 2 + 1];
                    if (part == 0) {
                        size_t off = ((size_t)bh * S_ + s) * D_ + d;
                        *(uint32_t*)&oQ0[off] = pack2h(x0, x1);
                    } else if (part == 1) {
                        size_t off = ((size_t)bh * S_ + s) * D_ + d;
                        *(uint32_t*)&oK0[off] = pack2h(x0, x1);
                    } else {
                        size_t offa = ((size_t)bh * D_ + d) * S_ + s;
                        size_t offb = ((size_t)bh * D_ + d + 1) * S_ + s;
                        oV0[offa] = __float2half_rn(x0);
                        oV0[offb] = __float2half_rn(x1);
                    }
                }
            }
        }
    }
}

// ---------------------------------------------------------------------------
// Kernel 3: fp16 tensor-core flash attention, single product per stage.
// Grid (S/128, 32 bh). 256 threads = 8 warps; warp w owns q rows [16w,16w+16).
// QK^T = Q*K.  PV = P*V (P packed from C-frags).
// K/V tiles (16 KB/stage) in a 3-STAGE cp.async pipeline (prefetch distance
// 2 ≈ 1100 cyc slack vs ~600 cyc L2-hit latency); single barrier per tile.
// Epilogue: single-fp16 ctx for the plain-fp16 out-projection.
// ---------------------------------------------------------------------------
#define AQT 128
#define ASM_STAGE 16384     // K | V, each 8 KB
#define ASM_Q (3 * ASM_STAGE)
#define ASM_TOTAL (ASM_Q + 16384)   // 64 KB

__global__ __launch_bounds__(256)
void attn_mma_kernel(const __half* __restrict__ Qh,
                     const __half* __restrict__ Kh,
                     const __half* __restrict__ Vh,
                     __half* __restrict__ c0) {
    extern __shared__ char sm[];
    const uint32_t smb = smem_u32(sm);
    const int tid  = threadIdx.x;
    const int lane = tid & 31;
    const int wq   = tid >> 5;               // 0..7
    const int bh   = blockIdx.y;             // b*16 + h
    const int qb   = blockIdx.x * AQT;
    const size_t kbase = (size_t)bh * S_ * D_;   // Q/K [bh][s][d]
    const size_t vbase = (size_t)bh * D_ * S_;   // V  [bh][d][s]
    const int NKT = S_ / 64;                 // 32 key tiles

    // Issue K/V tile kc into stage kc%3 (one commit group per tile)
    auto issue = [&](int kc) {
        const uint32_t sb = smb + (kc % 3) * ASM_STAGE;
        #pragma unroll
        for (int i = 0; i < 2; i++) {
            int idx = tid + i * 256;         // 0..511
            int r = idx >> 3, c = idx & 7;
            uint32_t so = s128(r, c);
            cp16(sb + so,
                 Kh + kbase + (size_t)(kc * 64 + r) * D_ + c * 8);
            cp16(sb + 8192 + so,
                 Vh + vbase + (size_t)r * S_ + kc * 64 + c * 8);
        }
        CP_COMMIT();
    };

    // Stage Q tile [128][64] fp16 (own commit group)
    #pragma unroll
    for (int i = 0; i < 4; i++) {
        int idx = tid + i * 256;             // 0..1023
        int r = idx >> 3, c = idx & 7;
        cp16(smb + ASM_Q + s128(r, c),
             Qh + kbase + (size_t)(qb + r) * D_ + c * 8);
    }
    CP_COMMIT();
    issue(0);
    issue(1);
    CP_WAIT(2);        // Q resident (tiles 0,1 may still be in flight)
    __syncthreads();

    // Q fragments (held for the whole kernel)
    uint32_t qf[4][4];
    {
        const int rA = wq * 16 + (lane & 15);
        const int cA = lane >> 4;
        #pragma unroll
        for (int t = 0; t < 4; t++)
            ldsm4(qf[t], smb + ASM_Q + s128(rA, t * 2 + cA));
    }

    float acc[8][4];
    #pragma unroll
    for (int j = 0; j < 8; j++)
        #pragma unroll
        for (int q = 0; q < 4; q++) acc[j][q] = 0.f;
    float mrow[2] = {-1e30f, -1e30f};
    float lrow[2] = {0.f, 0.f};

    const int rB = (lane & 7) + ((lane >> 4) << 3);
    const int cB = (lane >> 3) & 1;

    for (int kc = 0; kc < NKT; kc++) {
        // stage kc ready; allow the one later group (kc+1) to stay in flight
        if (kc + 1 < NKT) { CP_WAIT(1); } else { CP_WAIT(0); }
        __syncthreads();    // publish stage kc + prove compute kc-1 done

        if (kc + 2 < NKT) issue(kc + 2);   // stage (kc+2)%3 == (kc-1)%3, free

        const uint32_t sb = smb + (kc % 3) * ASM_STAGE;

        // ---- Scores: s[16q x 64k] over d=64, single product ----
        float sc[8][4];
        #pragma unroll
        for (int j = 0; j < 8; j++)
            #pragma unroll
            for (int q = 0; q < 4; q++) sc[j][q] = 0.f;

        #pragma unroll
        for (int t = 0; t < 4; t++) {
            #pragma unroll
            for (int jj = 0; jj < 4; jj++) {
                uint32_t k0f[4];
                ldsm4(k0f, sb + s128(jj * 16 + rB, t * 2 + cB));
                mma_f16(sc[2 * jj],     qf[t], &k0f[0]);
                mma_f16(sc[2 * jj + 1], qf[t], &k0f[2]);
            }
        }

        // ---- Online softmax on fragments (rows r=lane>>2 and r+8) ----
        #pragma unroll
        for (int h2 = 0; h2 < 2; h2++) {
            float rm = sc[0][2 * h2];
            #pragma unroll
            for (int j = 0; j < 8; j++) {
                rm = fmaxf(rm, sc[j][2 * h2]);
                rm = fmaxf(rm, sc[j][2 * h2 + 1]);
            }
            rm = fmaxf(rm, __shfl_xor_sync(0xFFFFFFFFu, rm, 1));
            rm = fmaxf(rm, __shfl_xor_sync(0xFFFFFFFFu, rm, 2));
            float mnew = fmaxf(mrow[h2], rm);
            float al   = __expf(mrow[h2] - mnew);
            mrow[h2] = mnew;
            float rs = 0.f;
            #pragma unroll
            for (int j = 0; j < 8; j++) {
                float p0 = __expf(sc[j][2 * h2]     - mnew);
                float p1 = __expf(sc[j][2 * h2 + 1] - mnew);
                sc[j][2 * h2]     = p0;
                sc[j][2 * h2 + 1] = p1;
                rs += p0 + p1;
            }
            rs += __shfl_xor_sync(0xFFFFFFFFu, rs, 1);
            rs += __shfl_xor_sync(0xFFFFFFFFu, rs, 2);
            lrow[h2] = lrow[h2] * al + rs;
            #pragma unroll
            for (int j = 0; j < 8; j++) {
                acc[j][2 * h2]     *= al;
                acc[j][2 * h2 + 1] *= al;
            }
        }

        // ---- PV: ctx += P * V, single product; P packed from C-frags ----
        #pragma unroll
        for (int t2 = 0; t2 < 4; t2++) {
            uint32_t ah[4];
            ah[0] = pack2h(sc[2 * t2][0],     sc[2 * t2][1]);
            ah[1] = pack2h(sc[2 * t2][2],     sc[2 * t2][3]);
            ah[2] = pack2h(sc[2 * t2 + 1][0], sc[2 * t2 + 1][1]);
            ah[3] = pack2h(sc[2 * t2 + 1][2], sc[2 * t2 + 1][3]);
            #pragma unroll
            for (int jj = 0; jj < 4; jj++) {
                uint32_t v0f[4];
                ldsm4(v0f, sb + 8192 + s128(jj * 16 + rB, t2 * 2 + cB));
                mma_f16(acc[2 * jj],     ah, &v0f[0]);
                mma_f16(acc[2 * jj + 1], ah, &v0f[2]);
            }
        }
        // no trailing barrier: next iteration's barrier protects stage reuse
    }

    // ---- Epilogue: normalize, single fp16 into c0 [NROWS][HD] ----
    const int b = bh >> 4, h = bh & 15;
    const float inv0 = 1.f / lrow[0];
    const float inv1 = 1.f / lrow[1];
    const int r  = lane >> 2;
    const int c2 = (lane & 3) * 2;
    #pragma unroll
    for (int j = 0; j < 8; j++) {
        const int d = j * 8 + c2;
        const int qg = qb + wq * 16 + r;
        size_t off0 = (size_t)(qg * 2 + b) * HD_ + h * 64 + d;
        size_t off1 = (size_t)((qg + 8) * 2 + b) * HD_ + h * 64 + d;
        *(uint32_t*)&c0[off0] = pack2h(acc[j][0] * inv0, acc[j][1] * inv0);
        *(uint32_t*)&c0[off1] = pack2h(acc[j][2] * inv1, acc[j][3] * inv1);
    }
}

// ---------------------------------------------------------------------------
// kernel_launch
// ---------------------------------------------------------------------------
extern "C" void kernel_launch(void* const* d_in, const int* in_sizes, int n_in,
                              void* d_out, int out_size) {
    const float* x        = (const float*)d_in[0];   // [S,B,E]
    const float* ln_scale = (const float*)d_in[1];   // [E]
    const float* w_qkv    = (const float*)d_in[2];   // [E, 3*H*D]
    const float* w_out    = (const float*)d_in[3];   // [H*D, E]
    float* out = (float*)d_out;                      // [S,B,E]

    __half *p_a0, *p_wq, *p_wo;
    __half *pQ0, *pK0, *pV0, *p_c0;
    cudaGetSymbolAddress((void**)&p_a0, g_a0);
    cudaGetSymbolAddress((void**)&p_wq, g_wq);
    cudaGetSymbolAddress((void**)&p_wo, g_wo);
    cudaGetSymbolAddress((void**)&pQ0,  g_q0);
    cudaGetSymbolAddress((void**)&pK0,  g_k0);
    cudaGetSymbolAddress((void**)&pV0,  g_v0);
    cudaGetSymbolAddress((void**)&p_c0, g_c0);

    cudaFuncSetAttribute(mma_gemm_kernel<0>,
                         cudaFuncAttributeMaxDynamicSharedMemorySize, GSM_TOTAL);
    cudaFuncSetAttribute(mma_gemm_kernel<1>,
                         cudaFuncAttributeMaxDynamicSharedMemorySize, GSM_TOTAL);
    cudaFuncSetAttribute(attn_mma_kernel,
                         cudaFuncAttributeMaxDynamicSharedMemorySize, ASM_TOTAL);

    // 1. Fused preprocessing: LayerNorm->fp16 and both weight transposes
    pre_kernel<<<NROWS + 3072 + 1024, 256>>>(
        x, ln_scale, p_a0, w_qkv, p_wq, w_out, p_wo);

    // 2. QKV projection -> single-fp16 attention operands (V transposed)
    mma_gemm_kernel<1><<<dim3(Q3_ / GBN, NROWS / GBM), 256, GSM_TOTAL>>>(
        p_a0, p_wq, nullptr, pQ0, pK0, pV0, Q3_, E_);

    // 3. fp16 tensor-core flash attention (3-stage K/V pipeline)
    attn_mma_kernel<<<dim3(S_ / AQT, BH_), 256, ASM_TOTAL>>>(
        pQ0, pK0, pV0, p_c0);

    // 4. Output projection (fp32 out)
    mma_gemm_kernel<0><<<dim3(E_ / GBN, NROWS / GBM), 256, GSM_TOTAL>>>(
        p_c0, p_wo, out, nullptr, nullptr, nullptr, E_, HD_);
}